// round 7
// baseline (speedup 1.0000x reference)
#include <cuda_runtime.h>

typedef unsigned long long ull;

#define NMAX 50000
#define EMAX 400000
#define ETOTMAX (EMAX + NMAX)
#define CAP 1024

// ---------------- scratch (device globals; no allocation allowed) ----------------
__device__ __align__(16) float g_h1[NMAX * 256];
__device__ __align__(16) float g_agg[NMAX * 256];
__device__ float g_asrc1[NMAX * 2], g_adst1[NMAX * 2];

__device__ __align__(16) float g_hm[NMAX * 64];
__device__ __align__(16) float g_hl[NMAX * 64];
__device__ float g_asrc_mu[NMAX], g_adst_mu[NMAX];
__device__ float g_asrc_ls[NMAX], g_adst_ls[NMAX];

__device__ int g_cnt[NMAX];
__device__ int g_tmp[NMAX];
__device__ int g_bsum[64], g_boff[64];
__device__ int g_ofs[NMAX + 1];
__device__ int g_cur[NMAX];
__device__ int g_src[ETOTMAX];

// ---------------- helpers ----------------
__device__ __forceinline__ float lrelu(float v) { return v > 0.f ? v : 0.2f * v; }
__device__ __forceinline__ float wredsum(float v) {
#pragma unroll
    for (int o = 16; o; o >>= 1) v += __shfl_xor_sync(0xFFFFFFFFu, v, o);
    return v;
}
__device__ __forceinline__ float wredmax(float v) {
#pragma unroll
    for (int o = 16; o; o >>= 1) v = fmaxf(v, __shfl_xor_sync(0xFFFFFFFFu, v, o));
    return v;
}
__device__ __forceinline__ ull pack2(float lo, float hi) {
    ull r; asm("mov.b64 %0, {%1, %2};" : "=l"(r) : "f"(lo), "f"(hi)); return r;
}
__device__ __forceinline__ void unpack2(ull v, float& lo, float& hi) {
    asm("mov.b64 {%0, %1}, %2;" : "=f"(lo), "=f"(hi) : "l"(v));
}
__device__ __forceinline__ void ffma2(ull& d, ull a, ull b) {
    asm("fma.rn.f32x2 %0, %1, %2, %0;" : "+l"(d) : "l"(a), "l"(b));
}

// ---------------- CSR build (unchanged, proven) ----------------
__global__ void prep(int n) {
    int i = blockIdx.x * blockDim.x + threadIdx.x;
    if (i < n) g_cnt[i] = 0;
}
__global__ void kcount(const int* __restrict__ ei, int E0, int Et) {
    int e = blockIdx.x * blockDim.x + threadIdx.x;
    if (e >= Et) return;
    int d = (e < E0) ? ei[E0 + e] : (e - E0);
    atomicAdd(&g_cnt[d], 1);
}
__global__ void scanA(int n) {
    __shared__ int wsum[32];
    int tid = threadIdx.x, lane = tid & 31, warp = tid >> 5;
    int i = blockIdx.x * 1024 + tid;
    int v = (i < n) ? g_cnt[i] : 0;
    int x = v;
#pragma unroll
    for (int o = 1; o < 32; o <<= 1) {
        int t = __shfl_up_sync(0xFFFFFFFFu, x, o);
        if (lane >= o) x += t;
    }
    if (lane == 31) wsum[warp] = x;
    __syncthreads();
    if (warp == 0) {
        int s = wsum[lane];
#pragma unroll
        for (int o = 1; o < 32; o <<= 1) {
            int t = __shfl_up_sync(0xFFFFFFFFu, s, o);
            if (lane >= o) s += t;
        }
        wsum[lane] = s;
    }
    __syncthreads();
    int pre = warp ? wsum[warp - 1] : 0;
    int incl = pre + x;
    if (i < n) g_tmp[i] = incl - v;
    if (tid == 1023) g_bsum[blockIdx.x] = incl;
}
__global__ void scanB(int nb) {
    __shared__ int w0tot;
    int tid = threadIdx.x, lane = tid & 31, warp = tid >> 5;
    int v = (tid < nb) ? g_bsum[tid] : 0;
    int x = v;
#pragma unroll
    for (int o = 1; o < 32; o <<= 1) {
        int t = __shfl_up_sync(0xFFFFFFFFu, x, o);
        if (lane >= o) x += t;
    }
    if (warp == 0 && lane == 31) w0tot = x;
    __syncthreads();
    int excl = x - v + (warp ? w0tot : 0);
    if (tid < nb) g_boff[tid] = excl;
}
__global__ void scanC(int n, int Et) {
    int i = blockIdx.x * blockDim.x + threadIdx.x;
    if (i < n) {
        int off = g_tmp[i] + g_boff[i >> 10];
        g_ofs[i] = off;
        g_cur[i] = off;
    }
    if (i == 0) g_ofs[n] = Et;
}
__global__ void kfill(const int* __restrict__ ei, int E0, int Et) {
    int e = blockIdx.x * blockDim.x + threadIdx.x;
    if (e >= Et) return;
    int s = (e < E0) ? ei[e] : (e - E0);
    int d = (e < E0) ? ei[E0 + e] : (e - E0);
    int pos = atomicAdd(&g_cur[d], 1);
    g_src[pos] = s;
}

// ---------------- GEMM1 (FFMA2, N-pair packed): h1 = x @ W1 + attention dots ---
// 256 threads = 8 warps; warp wi owns 8 nodes (M-tile 64). Lane owns column
// pairs {lane, lane+32, lane+64, lane+96} (cols 2p, 2p+1). K chunked by 16.
__global__ __launch_bounds__(256, 2) void gemm1(
    const float* __restrict__ x, const float* __restrict__ W1,
    const float* __restrict__ attS, const float* __restrict__ attD, int n)
{
    __shared__ __align__(16) ull xd[16][64];    // [kk][node], x duplicated (v,v)
    __shared__ __align__(16) ull ws[16][128];   // [kk][colpair]
    const int tid = threadIdx.x, lane = tid & 31, wi = tid >> 5;
    const int n0 = blockIdx.x * 64;
    const int nn = min(64, n - n0);

    ull acc[8][4];
#pragma unroll
    for (int i = 0; i < 8; i++)
#pragma unroll
        for (int p = 0; p < 4; p++) acc[i][p] = 0ull;

    for (int k0 = 0; k0 < 128; k0 += 16) {
        __syncthreads();
#pragma unroll
        for (int j = 0; j < 4; j++) {           // 1024 x entries
            int idx = tid + j * 256;
            int node = idx & 63, kk = idx >> 6;
            float v = (node < nn) ? x[(long)(n0 + node) * 128 + k0 + kk] : 0.f;
            xd[kk][node] = pack2(v, v);
        }
#pragma unroll
        for (int j = 0; j < 8; j++) {           // 2048 W pairs
            int idx = tid + j * 256;
            int cp = idx & 127, kk = idx >> 7;
            ws[kk][cp] = ((const ull*)(W1 + (long)(k0 + kk) * 256))[cp];
        }
        __syncthreads();
#pragma unroll 4
        for (int kk = 0; kk < 16; kk++) {
            ulonglong2 x01 = *(const ulonglong2*)&xd[kk][wi * 8 + 0];
            ulonglong2 x23 = *(const ulonglong2*)&xd[kk][wi * 8 + 2];
            ulonglong2 x45 = *(const ulonglong2*)&xd[kk][wi * 8 + 4];
            ulonglong2 x67 = *(const ulonglong2*)&xd[kk][wi * 8 + 6];
            ull w0 = ws[kk][lane];
            ull w1 = ws[kk][lane + 32];
            ull w2 = ws[kk][lane + 64];
            ull w3 = ws[kk][lane + 96];
            ffma2(acc[0][0], x01.x, w0); ffma2(acc[0][1], x01.x, w1);
            ffma2(acc[0][2], x01.x, w2); ffma2(acc[0][3], x01.x, w3);
            ffma2(acc[1][0], x01.y, w0); ffma2(acc[1][1], x01.y, w1);
            ffma2(acc[1][2], x01.y, w2); ffma2(acc[1][3], x01.y, w3);
            ffma2(acc[2][0], x23.x, w0); ffma2(acc[2][1], x23.x, w1);
            ffma2(acc[2][2], x23.x, w2); ffma2(acc[2][3], x23.x, w3);
            ffma2(acc[3][0], x23.y, w0); ffma2(acc[3][1], x23.y, w1);
            ffma2(acc[3][2], x23.y, w2); ffma2(acc[3][3], x23.y, w3);
            ffma2(acc[4][0], x45.x, w0); ffma2(acc[4][1], x45.x, w1);
            ffma2(acc[4][2], x45.x, w2); ffma2(acc[4][3], x45.x, w3);
            ffma2(acc[5][0], x45.y, w0); ffma2(acc[5][1], x45.y, w1);
            ffma2(acc[5][2], x45.y, w2); ffma2(acc[5][3], x45.y, w3);
            ffma2(acc[6][0], x67.x, w0); ffma2(acc[6][1], x67.x, w1);
            ffma2(acc[6][2], x67.x, w2); ffma2(acc[6][3], x67.x, w3);
            ffma2(acc[7][0], x67.y, w0); ffma2(acc[7][1], x67.y, w1);
            ffma2(acc[7][2], x67.y, w2); ffma2(acc[7][3], x67.y, w3);
        }
    }

    // epilogue: cols of pair p are (2p, 2p+1); p = lane + 32*j.
    float aS[4][2], aD[4][2];
#pragma unroll
    for (int j = 0; j < 4; j++) {
        int p = lane + 32 * j;
        aS[j][0] = attS[2 * p]; aS[j][1] = attS[2 * p + 1];
        aD[j][0] = attD[2 * p]; aD[j][1] = attD[2 * p + 1];
    }
#pragma unroll
    for (int i = 0; i < 8; i++) {
        int node = wi * 8 + i;
        float l0, h0, l1, h1, l2, h2, l3, h3;
        unpack2(acc[i][0], l0, h0); unpack2(acc[i][1], l1, h1);
        unpack2(acc[i][2], l2, h2); unpack2(acc[i][3], l3, h3);
        // head 0 = cols 0..127 (pairs 0..63 = j 0,1); head 1 = j 2,3
        float ps0 = l0 * aS[0][0] + h0 * aS[0][1] + l1 * aS[1][0] + h1 * aS[1][1];
        float pd0 = l0 * aD[0][0] + h0 * aD[0][1] + l1 * aD[1][0] + h1 * aD[1][1];
        float ps1 = l2 * aS[2][0] + h2 * aS[2][1] + l3 * aS[3][0] + h3 * aS[3][1];
        float pd1 = l2 * aD[2][0] + h2 * aD[2][1] + l3 * aD[3][0] + h3 * aD[3][1];
        ps0 = wredsum(ps0); pd0 = wredsum(pd0);
        ps1 = wredsum(ps1); pd1 = wredsum(pd1);
        if (node < nn) {
            if (lane == 0) {
                int gn = n0 + node;
                g_asrc1[gn * 2 + 0] = ps0; g_asrc1[gn * 2 + 1] = ps1;
                g_adst1[gn * 2 + 0] = pd0; g_adst1[gn * 2 + 1] = pd1;
            }
            ull* dst = (ull*)(g_h1 + (long)(n0 + node) * 256);
            dst[lane] = acc[i][0];
            dst[lane + 32] = acc[i][1];
            dst[lane + 64] = acc[i][2];
            dst[lane + 96] = acc[i][3];
        }
    }
}

// ---------------- gather1 (unchanged, proven) ----------------
__global__ __launch_bounds__(256) void gather1(const float* __restrict__ b1) {
    __shared__ int   s_src[CAP];
    __shared__ float s_w0[CAP], s_w1[CAP];
    __shared__ float par[6];
    const int d = blockIdx.x;
    const int tid = threadIdx.x, lane = tid & 31;
    const int beg = g_ofs[d];
    const int deg = g_ofs[d + 1] - beg;

    if (tid < 32) {
        float ad0 = g_adst1[2 * d], ad1 = g_adst1[2 * d + 1];
        float m0 = -1e30f, m1 = -1e30f;
        for (int i = lane; i < deg; i += 32) {
            int s = g_src[beg + i];
            float2 a = ((const float2*)g_asrc1)[s];
            float v0 = lrelu(a.x + ad0), v1 = lrelu(a.y + ad1);
            if (i < CAP) { s_src[i] = s; s_w0[i] = v0; s_w1[i] = v1; }
            m0 = fmaxf(m0, v0); m1 = fmaxf(m1, v1);
        }
        m0 = wredmax(m0); m1 = wredmax(m1);
        float t0 = 0.f, t1 = 0.f;
        for (int i = lane; i < deg; i += 32) {
            float v0, v1;
            if (i < CAP) { v0 = s_w0[i]; v1 = s_w1[i]; }
            else {
                int s = g_src[beg + i];
                float2 a = ((const float2*)g_asrc1)[s];
                v0 = lrelu(a.x + ad0); v1 = lrelu(a.y + ad1);
            }
            float w0 = __expf(v0 - m0), w1 = __expf(v1 - m1);
            if (i < CAP) { s_w0[i] = w0; s_w1[i] = w1; }
            t0 += w0; t1 += w1;
        }
        t0 = wredsum(t0); t1 = wredsum(t1);
        if (lane == 0) {
            par[0] = m0; par[1] = m1;
            par[2] = 1.f / (t0 + 1e-16f); par[3] = 1.f / (t1 + 1e-16f);
            par[4] = ad0; par[5] = ad1;
        }
    }
    __syncthreads();

    const int h = tid >> 7;
    const float* sw = h ? s_w1 : s_w0;
    const float inv = par[2 + h];
    const float* hbase = g_h1 + tid;
    float a0 = 0.f, a1 = 0.f, a2 = 0.f, a3 = 0.f;
    const int dc = min(deg, CAP);
    int i = 0;
    for (; i + 4 <= dc; i += 4) {
        int s0 = s_src[i], s1 = s_src[i + 1], s2 = s_src[i + 2], s3 = s_src[i + 3];
        float w0 = sw[i], w1 = sw[i + 1], w2 = sw[i + 2], w3 = sw[i + 3];
        float v0 = hbase[(long)s0 * 256];
        float v1 = hbase[(long)s1 * 256];
        float v2 = hbase[(long)s2 * 256];
        float v3 = hbase[(long)s3 * 256];
        a0 += w0 * v0; a1 += w1 * v1; a2 += w2 * v2; a3 += w3 * v3;
    }
    for (; i < dc; i++) a0 += sw[i] * hbase[(long)s_src[i] * 256];
    if (deg > CAP) {
        float m = par[h], adh = par[4 + h];
        for (int j = CAP; j < deg; j++) {
            int s = g_src[beg + j];
            float v = lrelu(g_asrc1[2 * s + h] + adh);
            a0 += __expf(v - m) * hbase[(long)s * 256];
        }
    }
    float acc = (a0 + a1) + (a2 + a3);
    float val = acc * inv + b1[tid];
    g_agg[(long)d * 256 + tid] = val > 0.f ? val : expm1f(val);
}

// ---------------- GEMM2 (FFMA2): [hm|hl] = agg @ [Wm|Wl] + attention dots ------
// 256 threads = 8 warps; warp wi owns 8 nodes (M-tile 64). Lane owns pair
// {lane} of mu cols (2lane, 2lane+1) and pair {lane+32} of ls cols.
__global__ __launch_bounds__(256, 2) void gemm2(
    const float* __restrict__ Wm, const float* __restrict__ Wl,
    const float* __restrict__ aSm, const float* __restrict__ aDm,
    const float* __restrict__ aSl, const float* __restrict__ aDl, int n)
{
    __shared__ __align__(16) ull xd[16][64];    // [kk][node]
    __shared__ __align__(16) ull ws[16][64];    // [kk][cp]  cp<32 mu, cp>=32 ls
    const int tid = threadIdx.x, lane = tid & 31, wi = tid >> 5;
    const int n0 = blockIdx.x * 64;
    const int nn = min(64, n - n0);

    ull acc[8][2];
#pragma unroll
    for (int i = 0; i < 8; i++) { acc[i][0] = 0ull; acc[i][1] = 0ull; }

    for (int k0 = 0; k0 < 256; k0 += 16) {
        __syncthreads();
#pragma unroll
        for (int j = 0; j < 4; j++) {           // 1024 x entries
            int idx = tid + j * 256;
            int node = idx & 63, kk = idx >> 6;
            float v = (node < nn) ? g_agg[(long)(n0 + node) * 256 + k0 + kk] : 0.f;
            xd[kk][node] = pack2(v, v);
        }
#pragma unroll
        for (int j = 0; j < 4; j++) {           // 1024 W pairs
            int idx = tid + j * 256;
            int cp = idx & 63, kk = idx >> 6;
            ws[kk][cp] = (cp < 32)
                ? ((const ull*)(Wm + (long)(k0 + kk) * 64))[cp]
                : ((const ull*)(Wl + (long)(k0 + kk) * 64))[cp - 32];
        }
        __syncthreads();
#pragma unroll 4
        for (int kk = 0; kk < 16; kk++) {
            ulonglong2 x01 = *(const ulonglong2*)&xd[kk][wi * 8 + 0];
            ulonglong2 x23 = *(const ulonglong2*)&xd[kk][wi * 8 + 2];
            ulonglong2 x45 = *(const ulonglong2*)&xd[kk][wi * 8 + 4];
            ulonglong2 x67 = *(const ulonglong2*)&xd[kk][wi * 8 + 6];
            ull w0 = ws[kk][lane];
            ull w1 = ws[kk][lane + 32];
            ffma2(acc[0][0], x01.x, w0); ffma2(acc[0][1], x01.x, w1);
            ffma2(acc[1][0], x01.y, w0); ffma2(acc[1][1], x01.y, w1);
            ffma2(acc[2][0], x23.x, w0); ffma2(acc[2][1], x23.x, w1);
            ffma2(acc[3][0], x23.y, w0); ffma2(acc[3][1], x23.y, w1);
            ffma2(acc[4][0], x45.x, w0); ffma2(acc[4][1], x45.x, w1);
            ffma2(acc[5][0], x45.y, w0); ffma2(acc[5][1], x45.y, w1);
            ffma2(acc[6][0], x67.x, w0); ffma2(acc[6][1], x67.x, w1);
            ffma2(acc[7][0], x67.y, w0); ffma2(acc[7][1], x67.y, w1);
        }
    }

    // epilogue
    const float sm0 = aSm[2 * lane], sm1 = aSm[2 * lane + 1];
    const float dm0 = aDm[2 * lane], dm1 = aDm[2 * lane + 1];
    const float sl0 = aSl[2 * lane], sl1 = aSl[2 * lane + 1];
    const float dl0 = aDl[2 * lane], dl1 = aDl[2 * lane + 1];
#pragma unroll
    for (int i = 0; i < 8; i++) {
        int node = wi * 8 + i;
        float lm, hm, ll, hl;
        unpack2(acc[i][0], lm, hm);
        unpack2(acc[i][1], ll, hl);
        float psm = lm * sm0 + hm * sm1;
        float pdm = lm * dm0 + hm * dm1;
        float psl = ll * sl0 + hl * sl1;
        float pdl = ll * dl0 + hl * dl1;
        psm = wredsum(psm); pdm = wredsum(pdm);
        psl = wredsum(psl); pdl = wredsum(pdl);
        if (node < nn) {
            int gn = n0 + node;
            if (lane == 0) {
                g_asrc_mu[gn] = psm; g_adst_mu[gn] = pdm;
                g_asrc_ls[gn] = psl; g_adst_ls[gn] = pdl;
            }
            ((ull*)(g_hm + (long)gn * 64))[lane] = acc[i][0];
            ((ull*)(g_hl + (long)gn * 64))[lane] = acc[i][1];
        }
    }
}

// ---------------- gather2 (unchanged, proven) ----------------
__global__ __launch_bounds__(128) void gather2(
    float* __restrict__ out, const float* __restrict__ bm,
    const float* __restrict__ bl, int n)
{
    __shared__ int   s_src[CAP];
    __shared__ float s_wm[CAP], s_wl[CAP];
    __shared__ float par[6];
    const int d = blockIdx.x;
    const int tid = threadIdx.x, lane = tid & 31;
    const int beg = g_ofs[d];
    const int deg = g_ofs[d + 1] - beg;

    if (tid < 32) {
        float adm = g_adst_mu[d], adl = g_adst_ls[d];
        float mm = -1e30f, ml = -1e30f;
        for (int i = lane; i < deg; i += 32) {
            int s = g_src[beg + i];
            float vm = lrelu(g_asrc_mu[s] + adm);
            float vl = lrelu(g_asrc_ls[s] + adl);
            if (i < CAP) { s_src[i] = s; s_wm[i] = vm; s_wl[i] = vl; }
            mm = fmaxf(mm, vm); ml = fmaxf(ml, vl);
        }
        mm = wredmax(mm); ml = wredmax(ml);
        float tm = 0.f, tl = 0.f;
        for (int i = lane; i < deg; i += 32) {
            float vm, vl;
            if (i < CAP) { vm = s_wm[i]; vl = s_wl[i]; }
            else {
                int s = g_src[beg + i];
                vm = lrelu(g_asrc_mu[s] + adm);
                vl = lrelu(g_asrc_ls[s] + adl);
            }
            float wm = __expf(vm - mm), wl = __expf(vl - ml);
            if (i < CAP) { s_wm[i] = wm; s_wl[i] = wl; }
            tm += wm; tl += wl;
        }
        tm = wredsum(tm); tl = wredsum(tl);
        if (lane == 0) {
            par[0] = mm; par[1] = ml;
            par[2] = 1.f / (tm + 1e-16f); par[3] = 1.f / (tl + 1e-16f);
            par[4] = adm; par[5] = adl;
        }
    }
    __syncthreads();

    const int grp = tid >> 6;         // 0 = mu, 1 = ls
    const int c = tid & 63;
    const float* hb = grp ? g_hl : g_hm;
    const float* sw = grp ? s_wl : s_wm;
    const float inv = par[2 + grp];
    const float* hbase = hb + c;
    float a0 = 0.f, a1 = 0.f, a2 = 0.f, a3 = 0.f;
    const int dc = min(deg, CAP);
    int i = 0;
    for (; i + 4 <= dc; i += 4) {
        int s0 = s_src[i], s1 = s_src[i + 1], s2 = s_src[i + 2], s3 = s_src[i + 3];
        float w0 = sw[i], w1 = sw[i + 1], w2 = sw[i + 2], w3 = sw[i + 3];
        float v0 = hbase[(long)s0 * 64];
        float v1 = hbase[(long)s1 * 64];
        float v2 = hbase[(long)s2 * 64];
        float v3 = hbase[(long)s3 * 64];
        a0 += w0 * v0; a1 += w1 * v1; a2 += w2 * v2; a3 += w3 * v3;
    }
    for (; i < dc; i++) a0 += sw[i] * hbase[(long)s_src[i] * 64];
    if (deg > CAP) {
        float m = par[grp], adh = par[4 + grp];
        const float* asc = grp ? g_asrc_ls : g_asrc_mu;
        for (int j2 = CAP; j2 < deg; j2++) {
            int s = g_src[beg + j2];
            float v = lrelu(asc[s] + adh);
            a0 += __expf(v - m) * hbase[(long)s * 64];
        }
    }
    float acc = (a0 + a1) + (a2 + a3);
    float bias = grp ? bl[c] : bm[c];
    long off = grp ? ((long)(n + d) * 64 + c) : ((long)d * 64 + c);
    out[off] = acc * inv + bias;
}

// ---------------- launch ----------------
extern "C" void kernel_launch(void* const* d_in, const int* in_sizes, int n_in,
                              void* d_out, int out_size) {
    const float* x     = (const float*)d_in[0];
    const int*   ei    = (const int*)d_in[1];
    const float* W1    = (const float*)d_in[2];
    const float* attS1 = (const float*)d_in[3];
    const float* attD1 = (const float*)d_in[4];
    const float* b1    = (const float*)d_in[5];
    const float* Wm    = (const float*)d_in[6];
    const float* aSm   = (const float*)d_in[7];
    const float* aDm   = (const float*)d_in[8];
    const float* bm    = (const float*)d_in[9];
    const float* Wl    = (const float*)d_in[10];
    const float* aSl   = (const float*)d_in[11];
    const float* aDl   = (const float*)d_in[12];
    const float* bl    = (const float*)d_in[13];
    float* out = (float*)d_out;

    int n  = in_sizes[0] / 128;
    int E0 = in_sizes[1] / 2;
    int Et = E0 + n;
    int eb = (Et + 255) / 256;
    int nb = (n + 1023) / 1024;

    prep<<<nb, 1024>>>(n);
    kcount<<<eb, 256>>>(ei, E0, Et);
    scanA<<<nb, 1024>>>(n);
    scanB<<<1, 64>>>(nb);
    scanC<<<nb, 1024>>>(n, Et);
    kfill<<<eb, 256>>>(ei, E0, Et);

    gemm1<<<(n + 63) / 64, 256>>>(x, W1, attS1, attD1, n);
    gather1<<<n, 256>>>(b1);
    gemm2<<<(n + 63) / 64, 256>>>(Wm, Wl, aSm, aDm, aSl, aDl, n);
    gather2<<<n, 128>>>(out, bm, bl, n);
}

// round 15
// speedup vs baseline: 1.0204x; 1.0204x over previous
#include <cuda_runtime.h>

#define NMAX 50000
#define EMAX 400000
#define ETOTMAX (EMAX + NMAX)
#define CAP 1024

// ---------------- scratch (device globals; zero-initialized at module load) -----
__device__ __align__(16) float g_h1[NMAX * 256];
__device__ __align__(16) float g_agg[NMAX * 256];
__device__ float g_asrc1[NMAX * 2], g_adst1[NMAX * 2];

__device__ __align__(16) float g_hm[NMAX * 64];
__device__ __align__(16) float g_hl[NMAX * 64];
__device__ float g_asrc_mu[NMAX], g_adst_mu[NMAX];
__device__ float g_asrc_ls[NMAX], g_adst_ls[NMAX];

__device__ int g_cnt[NMAX];          // must be zero at entry; scanC re-zeroes
__device__ int g_tmp[NMAX];
__device__ int g_bsum[64];
__device__ int g_ofs[NMAX + 1];
__device__ int g_cur[NMAX];
__device__ int g_src[ETOTMAX];

// ---------------- helpers ----------------
__device__ __forceinline__ float lrelu(float v) { return v > 0.f ? v : 0.2f * v; }
__device__ __forceinline__ float wredsum(float v) {
#pragma unroll
    for (int o = 16; o; o >>= 1) v += __shfl_xor_sync(0xFFFFFFFFu, v, o);
    return v;
}
__device__ __forceinline__ float wredmax(float v) {
#pragma unroll
    for (int o = 16; o; o >>= 1) v = fmaxf(v, __shfl_xor_sync(0xFFFFFFFFu, v, o));
    return v;
}
__device__ __forceinline__ int wredsumi(int v) {
#pragma unroll
    for (int o = 16; o; o >>= 1) v += __shfl_xor_sync(0xFFFFFFFFu, v, o);
    return v;
}

// ---------------- CSR build ----------------
__global__ void kcount(const int* __restrict__ ei, int E0, int Et) {
    int e = blockIdx.x * blockDim.x + threadIdx.x;
    if (e >= Et) return;
    int d = (e < E0) ? ei[E0 + e] : (e - E0);
    atomicAdd(&g_cnt[d], 1);
}
// per-block exclusive scan of g_cnt (1024/block); block totals -> g_bsum
__global__ void scanA(int n) {
    __shared__ int wsum[32];
    int tid = threadIdx.x, lane = tid & 31, warp = tid >> 5;
    int i = blockIdx.x * 1024 + tid;
    int v = (i < n) ? g_cnt[i] : 0;
    int x = v;
#pragma unroll
    for (int o = 1; o < 32; o <<= 1) {
        int t = __shfl_up_sync(0xFFFFFFFFu, x, o);
        if (lane >= o) x += t;
    }
    if (lane == 31) wsum[warp] = x;
    __syncthreads();
    if (warp == 0) {
        int s = wsum[lane];
#pragma unroll
        for (int o = 1; o < 32; o <<= 1) {
            int t = __shfl_up_sync(0xFFFFFFFFu, s, o);
            if (lane >= o) s += t;
        }
        wsum[lane] = s;
    }
    __syncthreads();
    int pre = warp ? wsum[warp - 1] : 0;
    int incl = pre + x;
    if (i < n) g_tmp[i] = incl - v;
    if (tid == 1023) g_bsum[blockIdx.x] = incl;
}
// fused: per-block base = sum of g_bsum below; writes g_ofs/g_cur, zeroes g_cnt
__global__ void scanC(int n, int Et, int nb) {
    __shared__ int s_boff;
    int tid = threadIdx.x;
    if (tid < 32) {
        int acc = 0;
        for (int j = tid; j < blockIdx.x; j += 32) acc += g_bsum[j];
        acc = wredsumi(acc);
        if (tid == 0) s_boff = acc;
    }
    __syncthreads();
    int i = blockIdx.x * 1024 + tid;
    if (i < n) {
        int off = g_tmp[i] + s_boff;
        g_ofs[i] = off;
        g_cur[i] = off;
        g_cnt[i] = 0;                 // re-zero for the next call (replaces prep)
    }
    if (i == 0) g_ofs[n] = Et;
}
__global__ void kfill(const int* __restrict__ ei, int E0, int Et) {
    int e = blockIdx.x * blockDim.x + threadIdx.x;
    if (e >= Et) return;
    int s = (e < E0) ? ei[e] : (e - E0);
    int d = (e < E0) ? ei[E0 + e] : (e - E0);
    int pos = atomicAdd(&g_cur[d], 1);
    g_src[pos] = s;
}

// ---------------- GEMM1 (R5 proven scalar): h1 = x @ W1 + attention dots -------
__global__ void gemm1(const float* __restrict__ x, const float* __restrict__ W1,
                      const float* __restrict__ attS, const float* __restrict__ attD,
                      int n) {
    __shared__ float xs[8 * 128];
    __shared__ float redS[8][8];
    __shared__ float redD[8][8];
    const int tid = threadIdx.x;
    const int n0 = blockIdx.x * 8;
    const int nn = min(8, n - n0);

    for (int idx = tid; idx < nn * 128; idx += 256) xs[idx] = x[(long)n0 * 128 + idx];
    __syncthreads();

    const float av_s = attS[tid];
    const float av_d = attD[tid];

    float acc[8];
#pragma unroll
    for (int i = 0; i < 8; i++) acc[i] = 0.f;

#pragma unroll 4
    for (int k = 0; k < 128; k += 4) {
        float w0 = W1[(k + 0) * 256 + tid];
        float w1 = W1[(k + 1) * 256 + tid];
        float w2 = W1[(k + 2) * 256 + tid];
        float w3 = W1[(k + 3) * 256 + tid];
#pragma unroll
        for (int i = 0; i < 8; i++) {
            float4 xv = *(const float4*)&xs[i * 128 + k];
            acc[i] += xv.x * w0 + xv.y * w1 + xv.z * w2 + xv.w * w3;
        }
    }

    const int warp = tid >> 5, lane = tid & 31;
    for (int i = 0; i < nn; i++) {
        g_h1[(long)(n0 + i) * 256 + tid] = acc[i];
        float ss = acc[i] * av_s, sd = acc[i] * av_d;
#pragma unroll
        for (int o = 16; o; o >>= 1) {
            ss += __shfl_down_sync(0xFFFFFFFFu, ss, o);
            sd += __shfl_down_sync(0xFFFFFFFFu, sd, o);
        }
        if (lane == 0) { redS[warp][i] = ss; redD[warp][i] = sd; }
    }
    __syncthreads();
    if (tid < 32) {
        int i = tid & 7, h = (tid >> 3) & 1, isD = tid >> 4;
        if (i < nn) {
            float v = 0.f;
#pragma unroll
            for (int w = 0; w < 4; w++) v += isD ? redD[h * 4 + w][i] : redS[h * 4 + w][i];
            if (isD) g_adst1[(n0 + i) * 2 + h] = v;
            else     g_asrc1[(n0 + i) * 2 + h] = v;
        }
    }
}

// ---------------- gather1 (R5 proven): fused softmax + aggregate + bias + ELU ---
__global__ __launch_bounds__(256) void gather1(const float* __restrict__ b1) {
    __shared__ int   s_src[CAP];
    __shared__ float s_w0[CAP], s_w1[CAP];
    __shared__ float par[6];
    const int d = blockIdx.x;
    const int tid = threadIdx.x, lane = tid & 31;
    const int beg = g_ofs[d];
    const int deg = g_ofs[d + 1] - beg;

    if (tid < 32) {
        float ad0 = g_adst1[2 * d], ad1 = g_adst1[2 * d + 1];
        float m0 = -1e30f, m1 = -1e30f;
        for (int i = lane; i < deg; i += 32) {
            int s = g_src[beg + i];
            float2 a = ((const float2*)g_asrc1)[s];
            float v0 = lrelu(a.x + ad0), v1 = lrelu(a.y + ad1);
            if (i < CAP) { s_src[i] = s; s_w0[i] = v0; s_w1[i] = v1; }
            m0 = fmaxf(m0, v0); m1 = fmaxf(m1, v1);
        }
        m0 = wredmax(m0); m1 = wredmax(m1);
        float t0 = 0.f, t1 = 0.f;
        for (int i = lane; i < deg; i += 32) {
            float v0, v1;
            if (i < CAP) { v0 = s_w0[i]; v1 = s_w1[i]; }
            else {
                int s = g_src[beg + i];
                float2 a = ((const float2*)g_asrc1)[s];
                v0 = lrelu(a.x + ad0); v1 = lrelu(a.y + ad1);
            }
            float w0 = __expf(v0 - m0), w1 = __expf(v1 - m1);
            if (i < CAP) { s_w0[i] = w0; s_w1[i] = w1; }
            t0 += w0; t1 += w1;
        }
        t0 = wredsum(t0); t1 = wredsum(t1);
        if (lane == 0) {
            par[0] = m0; par[1] = m1;
            par[2] = 1.f / (t0 + 1e-16f); par[3] = 1.f / (t1 + 1e-16f);
            par[4] = ad0; par[5] = ad1;
        }
    }
    __syncthreads();

    const int h = tid >> 7;
    const float* sw = h ? s_w1 : s_w0;
    const float inv = par[2 + h];
    const float* hbase = g_h1 + tid;
    float a0 = 0.f, a1 = 0.f, a2 = 0.f, a3 = 0.f;
    const int dc = min(deg, CAP);
    int i = 0;
    for (; i + 4 <= dc; i += 4) {
        int s0 = s_src[i], s1 = s_src[i + 1], s2 = s_src[i + 2], s3 = s_src[i + 3];
        float w0 = sw[i], w1 = sw[i + 1], w2 = sw[i + 2], w3 = sw[i + 3];
        float v0 = hbase[(long)s0 * 256];
        float v1 = hbase[(long)s1 * 256];
        float v2 = hbase[(long)s2 * 256];
        float v3 = hbase[(long)s3 * 256];
        a0 += w0 * v0; a1 += w1 * v1; a2 += w2 * v2; a3 += w3 * v3;
    }
    for (; i < dc; i++) a0 += sw[i] * hbase[(long)s_src[i] * 256];
    if (deg > CAP) {
        float m = par[h], adh = par[4 + h];
        for (int j = CAP; j < deg; j++) {
            int s = g_src[beg + j];
            float v = lrelu(g_asrc1[2 * s + h] + adh);
            a0 += __expf(v - m) * hbase[(long)s * 256];
        }
    }
    float acc = (a0 + a1) + (a2 + a3);
    float val = acc * inv + b1[tid];
    g_agg[(long)d * 256 + tid] = val > 0.f ? val : expm1f(val);
}

// ---------------- GEMM2 (R5 proven scalar): [hm|hl] = agg @ [Wm|Wl] ------------
__global__ void gemm2(const float* __restrict__ Wm, const float* __restrict__ Wl,
                      const float* __restrict__ aSm, const float* __restrict__ aDm,
                      const float* __restrict__ aSl, const float* __restrict__ aDl,
                      int n) {
    __shared__ float hs[8 * 256];
    __shared__ float redS[4][8];
    __shared__ float redD[4][8];
    const int tid = threadIdx.x;
    const int n0 = blockIdx.x * 8;
    const int nn = min(8, n - n0);
    const int half = tid >> 6;
    const int j = tid & 63;

    for (int idx = tid; idx < nn * 256; idx += 128) hs[idx] = g_agg[(long)n0 * 256 + idx];
    __syncthreads();

    const float* W = half ? Wl : Wm;
    const float av_s = half ? aSl[j] : aSm[j];
    const float av_d = half ? aDl[j] : aDm[j];

    float acc[8];
#pragma unroll
    for (int i = 0; i < 8; i++) acc[i] = 0.f;

#pragma unroll 4
    for (int k = 0; k < 256; k += 4) {
        float w0 = W[(k + 0) * 64 + j];
        float w1 = W[(k + 1) * 64 + j];
        float w2 = W[(k + 2) * 64 + j];
        float w3 = W[(k + 3) * 64 + j];
#pragma unroll
        for (int i = 0; i < 8; i++) {
            float4 xv = *(const float4*)&hs[i * 256 + k];
            acc[i] += xv.x * w0 + xv.y * w1 + xv.z * w2 + xv.w * w3;
        }
    }

    const int warp = tid >> 5, lane = tid & 31;
    float* dstbuf = half ? g_hl : g_hm;
    for (int i = 0; i < nn; i++) {
        dstbuf[(long)(n0 + i) * 64 + j] = acc[i];
        float ss = acc[i] * av_s, sd = acc[i] * av_d;
#pragma unroll
        for (int o = 16; o; o >>= 1) {
            ss += __shfl_down_sync(0xFFFFFFFFu, ss, o);
            sd += __shfl_down_sync(0xFFFFFFFFu, sd, o);
        }
        if (lane == 0) { redS[warp][i] = ss; redD[warp][i] = sd; }
    }
    __syncthreads();
    if (tid < 32) {
        int i = tid & 7, code = tid >> 3;
        if (i < nn) {
            int node = n0 + i;
            if (code == 0) g_asrc_mu[node] = redS[0][i] + redS[1][i];
            if (code == 1) g_adst_mu[node] = redD[0][i] + redD[1][i];
            if (code == 2) g_asrc_ls[node] = redS[2][i] + redS[3][i];
            if (code == 3) g_adst_ls[node] = redD[2][i] + redD[3][i];
        }
    }
}

// ---------------- gather2 (R5 proven): fused softmax + aggregate + bias ---------
__global__ __launch_bounds__(128) void gather2(
    float* __restrict__ out, const float* __restrict__ bm,
    const float* __restrict__ bl, int n)
{
    __shared__ int   s_src[CAP];
    __shared__ float s_wm[CAP], s_wl[CAP];
    __shared__ float par[6];
    const int d = blockIdx.x;
    const int tid = threadIdx.x, lane = tid & 31;
    const int beg = g_ofs[d];
    const int deg = g_ofs[d + 1] - beg;

    if (tid < 32) {
        float adm = g_adst_mu[d], adl = g_adst_ls[d];
        float mm = -1e30f, ml = -1e30f;
        for (int i = lane; i < deg; i += 32) {
            int s = g_src[beg + i];
            float vm = lrelu(g_asrc_mu[s] + adm);
            float vl = lrelu(g_asrc_ls[s] + adl);
            if (i < CAP) { s_src[i] = s; s_wm[i] = vm; s_wl[i] = vl; }
            mm = fmaxf(mm, vm); ml = fmaxf(ml, vl);
        }
        mm = wredmax(mm); ml = wredmax(ml);
        float tm = 0.f, tl = 0.f;
        for (int i = lane; i < deg; i += 32) {
            float vm, vl;
            if (i < CAP) { vm = s_wm[i]; vl = s_wl[i]; }
            else {
                int s = g_src[beg + i];
                vm = lrelu(g_asrc_mu[s] + adm);
                vl = lrelu(g_asrc_ls[s] + adl);
            }
            float wm = __expf(vm - mm), wl = __expf(vl - ml);
            if (i < CAP) { s_wm[i] = wm; s_wl[i] = wl; }
            tm += wm; tl += wl;
        }
        tm = wredsum(tm); tl = wredsum(tl);
        if (lane == 0) {
            par[0] = mm; par[1] = ml;
            par[2] = 1.f / (tm + 1e-16f); par[3] = 1.f / (tl + 1e-16f);
            par[4] = adm; par[5] = adl;
        }
    }
    __syncthreads();

    const int grp = tid >> 6;         // 0 = mu, 1 = ls
    const int c = tid & 63;
    const float* hb = grp ? g_hl : g_hm;
    const float* sw = grp ? s_wl : s_wm;
    const float inv = par[2 + grp];
    const float* hbase = hb + c;
    float a0 = 0.f, a1 = 0.f, a2 = 0.f, a3 = 0.f;
    const int dc = min(deg, CAP);
    int i = 0;
    for (; i + 4 <= dc; i += 4) {
        int s0 = s_src[i], s1 = s_src[i + 1], s2 = s_src[i + 2], s3 = s_src[i + 3];
        float w0 = sw[i], w1 = sw[i + 1], w2 = sw[i + 2], w3 = sw[i + 3];
        float v0 = hbase[(long)s0 * 64];
        float v1 = hbase[(long)s1 * 64];
        float v2 = hbase[(long)s2 * 64];
        float v3 = hbase[(long)s3 * 64];
        a0 += w0 * v0; a1 += w1 * v1; a2 += w2 * v2; a3 += w3 * v3;
    }
    for (; i < dc; i++) a0 += sw[i] * hbase[(long)s_src[i] * 64];
    if (deg > CAP) {
        float m = par[grp], adh = par[4 + grp];
        const float* asc = grp ? g_asrc_ls : g_asrc_mu;
        for (int j2 = CAP; j2 < deg; j2++) {
            int s = g_src[beg + j2];
            float v = lrelu(asc[s] + adh);
            a0 += __expf(v - m) * hbase[(long)s * 64];
        }
    }
    float acc = (a0 + a1) + (a2 + a3);
    float bias = grp ? bl[c] : bm[c];
    long off = grp ? ((long)(n + d) * 64 + c) : ((long)d * 64 + c);
    out[off] = acc * inv + bias;
}

// ---------------- launch ----------------
extern "C" void kernel_launch(void* const* d_in, const int* in_sizes, int n_in,
                              void* d_out, int out_size) {
    const float* x     = (const float*)d_in[0];
    const int*   ei    = (const int*)d_in[1];
    const float* W1    = (const float*)d_in[2];
    const float* attS1 = (const float*)d_in[3];
    const float* attD1 = (const float*)d_in[4];
    const float* b1    = (const float*)d_in[5];
    const float* Wm    = (const float*)d_in[6];
    const float* aSm   = (const float*)d_in[7];
    const float* aDm   = (const float*)d_in[8];
    const float* bm    = (const float*)d_in[9];
    const float* Wl    = (const float*)d_in[10];
    const float* aSl   = (const float*)d_in[11];
    const float* aDl   = (const float*)d_in[12];
    const float* bl    = (const float*)d_in[13];
    float* out = (float*)d_out;

    int n  = in_sizes[0] / 128;
    int E0 = in_sizes[1] / 2;
    int Et = E0 + n;
    int eb = (Et + 255) / 256;
    int nb = (n + 1023) / 1024;

    // launch order chosen so gemm1 is the 4th launch (ncu profiles launch #4)
    kcount<<<eb, 256>>>(ei, E0, Et);                       // 1
    scanA<<<nb, 1024>>>(n);                                // 2
    scanC<<<nb, 1024>>>(n, Et, nb);                        // 3 (fused scanB+scanC+prep)
    gemm1<<<(n + 7) / 8, 256>>>(x, W1, attS1, attD1, n);   // 4  <- profiled
    kfill<<<eb, 256>>>(ei, E0, Et);                        // 5
    gather1<<<n, 256>>>(b1);                               // 6
    gemm2<<<(n + 7) / 8, 128>>>(Wm, Wl, aSm, aDm, aSl, aDl, n); // 7
    gather2<<<n, 128>>>(out, bm, bl, n);                   // 8
}

// round 16
// speedup vs baseline: 1.0829x; 1.0612x over previous
#include <cuda_runtime.h>

#define NMAX 50000
#define EMAX 400000
#define ETOTMAX (EMAX + NMAX)
#define CAP 1024

// ---------------- scratch (device globals; zero-initialized at module load) -----
__device__ __align__(16) float g_h1[NMAX * 256];
__device__ __align__(16) float g_agg[NMAX * 256];
__device__ float g_asrc1[NMAX * 2], g_adst1[NMAX * 2];

__device__ __align__(16) float g_hm[NMAX * 64];
__device__ __align__(16) float g_hl[NMAX * 64];
__device__ float g_asrc_mu[NMAX], g_adst_mu[NMAX];
__device__ float g_asrc_ls[NMAX], g_adst_ls[NMAX];

__device__ int g_cnt[NMAX];          // must be zero at entry; scanC re-zeroes
__device__ int g_tmp[NMAX];
__device__ int g_bsum[64];
__device__ int g_ofs[NMAX + 1];
__device__ int g_cur[NMAX];
__device__ int g_src[ETOTMAX];

// ---------------- helpers ----------------
__device__ __forceinline__ float lrelu(float v) { return v > 0.f ? v : 0.2f * v; }
__device__ __forceinline__ float wredsum(float v) {
#pragma unroll
    for (int o = 16; o; o >>= 1) v += __shfl_xor_sync(0xFFFFFFFFu, v, o);
    return v;
}
__device__ __forceinline__ float wredmax(float v) {
#pragma unroll
    for (int o = 16; o; o >>= 1) v = fmaxf(v, __shfl_xor_sync(0xFFFFFFFFu, v, o));
    return v;
}
__device__ __forceinline__ int wredsumi(int v) {
#pragma unroll
    for (int o = 16; o; o >>= 1) v += __shfl_xor_sync(0xFFFFFFFFu, v, o);
    return v;
}

// ---------------- CSR build (proven R8/R15 config) ----------------
__global__ void kcount(const int* __restrict__ ei, int E0, int Et) {
    int e = blockIdx.x * blockDim.x + threadIdx.x;
    if (e >= Et) return;
    int d = (e < E0) ? ei[E0 + e] : (e - E0);
    atomicAdd(&g_cnt[d], 1);
}
__global__ void scanA(int n) {
    __shared__ int wsum[32];
    int tid = threadIdx.x, lane = tid & 31, warp = tid >> 5;
    int i = blockIdx.x * 1024 + tid;
    int v = (i < n) ? g_cnt[i] : 0;
    int x = v;
#pragma unroll
    for (int o = 1; o < 32; o <<= 1) {
        int t = __shfl_up_sync(0xFFFFFFFFu, x, o);
        if (lane >= o) x += t;
    }
    if (lane == 31) wsum[warp] = x;
    __syncthreads();
    if (warp == 0) {
        int s = wsum[lane];
#pragma unroll
        for (int o = 1; o < 32; o <<= 1) {
            int t = __shfl_up_sync(0xFFFFFFFFu, s, o);
            if (lane >= o) s += t;
        }
        wsum[lane] = s;
    }
    __syncthreads();
    int pre = warp ? wsum[warp - 1] : 0;
    int incl = pre + x;
    if (i < n) g_tmp[i] = incl - v;
    if (tid == 1023) g_bsum[blockIdx.x] = incl;
}
__global__ void scanC(int n, int Et, int nb) {
    __shared__ int s_boff;
    int tid = threadIdx.x;
    if (tid < 32) {
        int acc = 0;
        for (int j = tid; j < blockIdx.x; j += 32) acc += g_bsum[j];
        acc = wredsumi(acc);
        if (tid == 0) s_boff = acc;
    }
    __syncthreads();
    int i = blockIdx.x * 1024 + tid;
    if (i < n) {
        int off = g_tmp[i] + s_boff;
        g_ofs[i] = off;
        g_cur[i] = off;
        g_cnt[i] = 0;
    }
    if (i == 0) g_ofs[n] = Et;
}
__global__ void kfill(const int* __restrict__ ei, int E0, int Et) {
    int e = blockIdx.x * blockDim.x + threadIdx.x;
    if (e >= Et) return;
    int s = (e < E0) ? ei[e] : (e - E0);
    int d = (e < E0) ? ei[E0 + e] : (e - E0);
    int pos = atomicAdd(&g_cur[d], 1);
    g_src[pos] = s;
}

// ---------------- GEMM1 v3: column-register-blocked (C=4), M-tile 32 -----------
// 256 threads = 64 col-threads (cols ct, ct+64, ct+128, ct+192) x 4 node-groups
// of 8 nodes. Full x tile staged once; per 4-k chunk each warp issues 8 LDS-wf +
// 16 LDG-wf for 128 FFMA (0.1875 wf/FMA vs 0.375 before).
__global__ __launch_bounds__(256) void gemm1(
    const float* __restrict__ x, const float* __restrict__ W1,
    const float* __restrict__ attS, const float* __restrict__ attD, int n)
{
    __shared__ __align__(16) float xs[32 * 128];   // 16KB
    __shared__ float s_r[8][8][4];                 // [warp][node-in-group][q]
    const int tid = threadIdx.x;
    const int ct = tid & 63, ng = tid >> 6;
    const int warp = tid >> 5, lane = tid & 31;
    const int n0 = blockIdx.x * 32;
    const int nn = min(32, n - n0);

    for (int idx = tid; idx < 32 * 128; idx += 256) {
        int node = idx >> 7, k = idx & 127;
        xs[idx] = (node < nn) ? x[(long)(n0 + node) * 128 + k] : 0.f;
    }
    __syncthreads();

    float acc[8][4];
#pragma unroll
    for (int i = 0; i < 8; i++)
#pragma unroll
        for (int j = 0; j < 4; j++) acc[i][j] = 0.f;

    for (int k = 0; k < 128; k += 4) {
        float w[4][4];
#pragma unroll
        for (int kk = 0; kk < 4; kk++)
#pragma unroll
            for (int j = 0; j < 4; j++)
                w[kk][j] = W1[(long)(k + kk) * 256 + ct + 64 * j];
#pragma unroll
        for (int i = 0; i < 8; i++) {
            float4 xv = *(const float4*)&xs[(ng * 8 + i) * 128 + k];
#pragma unroll
            for (int j = 0; j < 4; j++)
                acc[i][j] += xv.x * w[0][j] + xv.y * w[1][j]
                           + xv.z * w[2][j] + xv.w * w[3][j];
        }
    }

    float aS[4], aD[4];
#pragma unroll
    for (int j = 0; j < 4; j++) { aS[j] = attS[ct + 64 * j]; aD[j] = attD[ct + 64 * j]; }

#pragma unroll
    for (int i = 0; i < 8; i++) {
        int node = ng * 8 + i;
        if (node < nn) {
#pragma unroll
            for (int j = 0; j < 4; j++)
                g_h1[(long)(n0 + node) * 256 + ct + 64 * j] = acc[i][j];
        }
        // head0 = cols 0..127 (j=0,1); head1 = cols 128..255 (j=2,3)
        float ps0 = acc[i][0] * aS[0] + acc[i][1] * aS[1];
        float pd0 = acc[i][0] * aD[0] + acc[i][1] * aD[1];
        float ps1 = acc[i][2] * aS[2] + acc[i][3] * aS[3];
        float pd1 = acc[i][2] * aD[2] + acc[i][3] * aD[3];
        ps0 = wredsum(ps0); pd0 = wredsum(pd0);
        ps1 = wredsum(ps1); pd1 = wredsum(pd1);
        if (lane == 0) {
            s_r[warp][i][0] = ps0; s_r[warp][i][1] = pd0;
            s_r[warp][i][2] = ps1; s_r[warp][i][3] = pd1;
        }
    }
    __syncthreads();
    if (tid < 128) {
        int node = tid >> 2, q = tid & 3;
        if (node < nn) {
            int g = node >> 3, i = node & 7;
            float v = s_r[2 * g][i][q] + s_r[2 * g + 1][i][q];
            int gn = n0 + node;
            if (q == 0)      g_asrc1[gn * 2 + 0] = v;
            else if (q == 1) g_adst1[gn * 2 + 0] = v;
            else if (q == 2) g_asrc1[gn * 2 + 1] = v;
            else             g_adst1[gn * 2 + 1] = v;
        }
    }
}

// ---------------- gather1 (R5 proven): fused softmax + aggregate + bias + ELU ---
__global__ __launch_bounds__(256) void gather1(const float* __restrict__ b1) {
    __shared__ int   s_src[CAP];
    __shared__ float s_w0[CAP], s_w1[CAP];
    __shared__ float par[6];
    const int d = blockIdx.x;
    const int tid = threadIdx.x, lane = tid & 31;
    const int beg = g_ofs[d];
    const int deg = g_ofs[d + 1] - beg;

    if (tid < 32) {
        float ad0 = g_adst1[2 * d], ad1 = g_adst1[2 * d + 1];
        float m0 = -1e30f, m1 = -1e30f;
        for (int i = lane; i < deg; i += 32) {
            int s = g_src[beg + i];
            float2 a = ((const float2*)g_asrc1)[s];
            float v0 = lrelu(a.x + ad0), v1 = lrelu(a.y + ad1);
            if (i < CAP) { s_src[i] = s; s_w0[i] = v0; s_w1[i] = v1; }
            m0 = fmaxf(m0, v0); m1 = fmaxf(m1, v1);
        }
        m0 = wredmax(m0); m1 = wredmax(m1);
        float t0 = 0.f, t1 = 0.f;
        for (int i = lane; i < deg; i += 32) {
            float v0, v1;
            if (i < CAP) { v0 = s_w0[i]; v1 = s_w1[i]; }
            else {
                int s = g_src[beg + i];
                float2 a = ((const float2*)g_asrc1)[s];
                v0 = lrelu(a.x + ad0); v1 = lrelu(a.y + ad1);
            }
            float w0 = __expf(v0 - m0), w1 = __expf(v1 - m1);
            if (i < CAP) { s_w0[i] = w0; s_w1[i] = w1; }
            t0 += w0; t1 += w1;
        }
        t0 = wredsum(t0); t1 = wredsum(t1);
        if (lane == 0) {
            par[0] = m0; par[1] = m1;
            par[2] = 1.f / (t0 + 1e-16f); par[3] = 1.f / (t1 + 1e-16f);
            par[4] = ad0; par[5] = ad1;
        }
    }
    __syncthreads();

    const int h = tid >> 7;
    const float* sw = h ? s_w1 : s_w0;
    const float inv = par[2 + h];
    const float* hbase = g_h1 + tid;
    float a0 = 0.f, a1 = 0.f, a2 = 0.f, a3 = 0.f;
    const int dc = min(deg, CAP);
    int i = 0;
    for (; i + 4 <= dc; i += 4) {
        int s0 = s_src[i], s1 = s_src[i + 1], s2 = s_src[i + 2], s3 = s_src[i + 3];
        float w0 = sw[i], w1 = sw[i + 1], w2 = sw[i + 2], w3 = sw[i + 3];
        float v0 = hbase[(long)s0 * 256];
        float v1 = hbase[(long)s1 * 256];
        float v2 = hbase[(long)s2 * 256];
        float v3 = hbase[(long)s3 * 256];
        a0 += w0 * v0; a1 += w1 * v1; a2 += w2 * v2; a3 += w3 * v3;
    }
    for (; i < dc; i++) a0 += sw[i] * hbase[(long)s_src[i] * 256];
    if (deg > CAP) {
        float m = par[h], adh = par[4 + h];
        for (int j = CAP; j < deg; j++) {
            int s = g_src[beg + j];
            float v = lrelu(g_asrc1[2 * s + h] + adh);
            a0 += __expf(v - m) * hbase[(long)s * 256];
        }
    }
    float acc = (a0 + a1) + (a2 + a3);
    float val = acc * inv + b1[tid];
    g_agg[(long)d * 256 + tid] = val > 0.f ? val : expm1f(val);
}

// ---------------- GEMM2 v3: column-register-blocked (C=2), M-tile 32 -----------
// 256 threads = 64 col-threads (mu col ct, ls col ct) x 4 node-groups x 8 nodes.
// Full 256-k tile staged (32KB). Per 4-k chunk per warp: 8 LDS-wf + 8 LDG-wf
// for 64 FFMA (0.25 wf/FMA), 8 warps/block (vs 4 before).
__global__ __launch_bounds__(256) void gemm2(
    const float* __restrict__ Wm, const float* __restrict__ Wl,
    const float* __restrict__ aSm, const float* __restrict__ aDm,
    const float* __restrict__ aSl, const float* __restrict__ aDl, int n)
{
    __shared__ __align__(16) float hs[32 * 256];   // 32KB
    __shared__ float s_r[8][8][4];
    const int tid = threadIdx.x;
    const int ct = tid & 63, ng = tid >> 6;
    const int warp = tid >> 5, lane = tid & 31;
    const int n0 = blockIdx.x * 32;
    const int nn = min(32, n - n0);

    for (int idx = tid; idx < 32 * 256; idx += 256) {
        int node = idx >> 8, k = idx & 255;
        hs[idx] = (node < nn) ? g_agg[(long)(n0 + node) * 256 + k] : 0.f;
    }
    __syncthreads();

    float acc[8][2];
#pragma unroll
    for (int i = 0; i < 8; i++) { acc[i][0] = 0.f; acc[i][1] = 0.f; }

    for (int k = 0; k < 256; k += 4) {
        float wm[4], wl[4];
#pragma unroll
        for (int kk = 0; kk < 4; kk++) {
            wm[kk] = Wm[(long)(k + kk) * 64 + ct];
            wl[kk] = Wl[(long)(k + kk) * 64 + ct];
        }
#pragma unroll
        for (int i = 0; i < 8; i++) {
            float4 xv = *(const float4*)&hs[(ng * 8 + i) * 256 + k];
            acc[i][0] += xv.x * wm[0] + xv.y * wm[1] + xv.z * wm[2] + xv.w * wm[3];
            acc[i][1] += xv.x * wl[0] + xv.y * wl[1] + xv.z * wl[2] + xv.w * wl[3];
        }
    }

    const float sm = aSm[ct], dm = aDm[ct];
    const float sl = aSl[ct], dl = aDl[ct];
#pragma unroll
    for (int i = 0; i < 8; i++) {
        int node = ng * 8 + i;
        if (node < nn) {
            g_hm[(long)(n0 + node) * 64 + ct] = acc[i][0];
            g_hl[(long)(n0 + node) * 64 + ct] = acc[i][1];
        }
        float psm = acc[i][0] * sm, pdm = acc[i][0] * dm;
        float psl = acc[i][1] * sl, pdl = acc[i][1] * dl;
        psm = wredsum(psm); pdm = wredsum(pdm);
        psl = wredsum(psl); pdl = wredsum(pdl);
        if (lane == 0) {
            s_r[warp][i][0] = psm; s_r[warp][i][1] = pdm;
            s_r[warp][i][2] = psl; s_r[warp][i][3] = pdl;
        }
    }
    __syncthreads();
    if (tid < 128) {
        int node = tid >> 2, q = tid & 3;
        if (node < nn) {
            int g = node >> 3, i = node & 7;
            float v = s_r[2 * g][i][q] + s_r[2 * g + 1][i][q];
            int gn = n0 + node;
            if (q == 0)      g_asrc_mu[gn] = v;
            else if (q == 1) g_adst_mu[gn] = v;
            else if (q == 2) g_asrc_ls[gn] = v;
            else             g_adst_ls[gn] = v;
        }
    }
}

// ---------------- gather2 (R5 proven): fused softmax + aggregate + bias ---------
__global__ __launch_bounds__(128) void gather2(
    float* __restrict__ out, const float* __restrict__ bm,
    const float* __restrict__ bl, int n)
{
    __shared__ int   s_src[CAP];
    __shared__ float s_wm[CAP], s_wl[CAP];
    __shared__ float par[6];
    const int d = blockIdx.x;
    const int tid = threadIdx.x, lane = tid & 31;
    const int beg = g_ofs[d];
    const int deg = g_ofs[d + 1] - beg;

    if (tid < 32) {
        float adm = g_adst_mu[d], adl = g_adst_ls[d];
        float mm = -1e30f, ml = -1e30f;
        for (int i = lane; i < deg; i += 32) {
            int s = g_src[beg + i];
            float vm = lrelu(g_asrc_mu[s] + adm);
            float vl = lrelu(g_asrc_ls[s] + adl);
            if (i < CAP) { s_src[i] = s; s_wm[i] = vm; s_wl[i] = vl; }
            mm = fmaxf(mm, vm); ml = fmaxf(ml, vl);
        }
        mm = wredmax(mm); ml = wredmax(ml);
        float tm = 0.f, tl = 0.f;
        for (int i = lane; i < deg; i += 32) {
            float vm, vl;
            if (i < CAP) { vm = s_wm[i]; vl = s_wl[i]; }
            else {
                int s = g_src[beg + i];
                vm = lrelu(g_asrc_mu[s] + adm);
                vl = lrelu(g_asrc_ls[s] + adl);
            }
            float wm = __expf(vm - mm), wl = __expf(vl - ml);
            if (i < CAP) { s_wm[i] = wm; s_wl[i] = wl; }
            tm += wm; tl += wl;
        }
        tm = wredsum(tm); tl = wredsum(tl);
        if (lane == 0) {
            par[0] = mm; par[1] = ml;
            par[2] = 1.f / (tm + 1e-16f); par[3] = 1.f / (tl + 1e-16f);
            par[4] = adm; par[5] = adl;
        }
    }
    __syncthreads();

    const int grp = tid >> 6;         // 0 = mu, 1 = ls
    const int c = tid & 63;
    const float* hb = grp ? g_hl : g_hm;
    const float* sw = grp ? s_wl : s_wm;
    const float inv = par[2 + grp];
    const float* hbase = hb + c;
    float a0 = 0.f, a1 = 0.f, a2 = 0.f, a3 = 0.f;
    const int dc = min(deg, CAP);
    int i = 0;
    for (; i + 4 <= dc; i += 4) {
        int s0 = s_src[i], s1 = s_src[i + 1], s2 = s_src[i + 2], s3 = s_src[i + 3];
        float w0 = sw[i], w1 = sw[i + 1], w2 = sw[i + 2], w3 = sw[i + 3];
        float v0 = hbase[(long)s0 * 64];
        float v1 = hbase[(long)s1 * 64];
        float v2 = hbase[(long)s2 * 64];
        float v3 = hbase[(long)s3 * 64];
        a0 += w0 * v0; a1 += w1 * v1; a2 += w2 * v2; a3 += w3 * v3;
    }
    for (; i < dc; i++) a0 += sw[i] * hbase[(long)s_src[i] * 64];
    if (deg > CAP) {
        float m = par[grp], adh = par[4 + grp];
        const float* asc = grp ? g_asrc_ls : g_asrc_mu;
        for (int j2 = CAP; j2 < deg; j2++) {
            int s = g_src[beg + j2];
            float v = lrelu(asc[s] + adh);
            a0 += __expf(v - m) * hbase[(long)s * 64];
        }
    }
    float acc = (a0 + a1) + (a2 + a3);
    float bias = grp ? bl[c] : bm[c];
    long off = grp ? ((long)(n + d) * 64 + c) : ((long)d * 64 + c);
    out[off] = acc * inv + bias;
}

// ---------------- launch ----------------
extern "C" void kernel_launch(void* const* d_in, const int* in_sizes, int n_in,
                              void* d_out, int out_size) {
    const float* x     = (const float*)d_in[0];
    const int*   ei    = (const int*)d_in[1];
    const float* W1    = (const float*)d_in[2];
    const float* attS1 = (const float*)d_in[3];
    const float* attD1 = (const float*)d_in[4];
    const float* b1    = (const float*)d_in[5];
    const float* Wm    = (const float*)d_in[6];
    const float* aSm   = (const float*)d_in[7];
    const float* aDm   = (const float*)d_in[8];
    const float* bm    = (const float*)d_in[9];
    const float* Wl    = (const float*)d_in[10];
    const float* aSl   = (const float*)d_in[11];
    const float* aDl   = (const float*)d_in[12];
    const float* bl    = (const float*)d_in[13];
    float* out = (float*)d_out;

    int n  = in_sizes[0] / 128;
    int E0 = in_sizes[1] / 2;
    int Et = E0 + n;
    int eb = (Et + 255) / 256;
    int nb = (n + 1023) / 1024;

    // gemm1 kept at launch #4 (the slot ncu profiles)
    kcount<<<eb, 256>>>(ei, E0, Et);                       // 1
    scanA<<<nb, 1024>>>(n);                                // 2
    scanC<<<nb, 1024>>>(n, Et, nb);                        // 3
    gemm1<<<(n + 31) / 32, 256>>>(x, W1, attS1, attD1, n); // 4  <- profiled
    kfill<<<eb, 256>>>(ei, E0, Et);                        // 5
    gather1<<<n, 256>>>(b1);                               // 6
    gemm2<<<(n + 31) / 32, 256>>>(Wm, Wl, aSm, aDm, aSl, aDl, n); // 7
    gather2<<<n, 128>>>(out, bm, bl, n);                   // 8
}